// round 3
// baseline (speedup 1.0000x reference)
#include <cuda_runtime.h>

// SpatialPool: fm[16,512,38,38] f32 (NCHW) -> out[16,1444,9*512] f32
// out[b, h*38+w, (di*3+dj)*512 + c] = fm[b, c, clamp(h+di-1,0,37), clamp(w+dj-1,0,37)]
//
// Stage 1: NCHW -> NHWC transpose into device scratch (coalesced both sides).
// Stage 2: coalesced 2KB-row gather from NHWC scratch with clamped neighbor
//          indexing; streaming stores to keep scratch resident in L2.

#define BB 16
#define CC 512
#define HH 38
#define WW 38
#define HWD 1444          // 38*38
#define C4 128            // 512/4 float4 per channel vector

__device__ float g_scratch[BB * HWD * CC];  // 47.3 MB NHWC staging

// ---------------------------------------------------------------------------
// Kernel 1: per-batch 512 x 1444 matrix transpose -> 1444 x 512
// ---------------------------------------------------------------------------
__global__ void sp_transpose_kernel(const float* __restrict__ fm) {
    __shared__ float tile[32][33];  // +1 pad: conflict-free transpose

    const int b  = blockIdx.z;
    const int s0 = blockIdx.x * 32;   // spatial (h*W+w), contiguous in fm
    const int c0 = blockIdx.y * 32;   // channel
    const int tx = threadIdx.x;
    const int ty = threadIdx.y;

    const float* src = fm + (size_t)b * CC * HWD;
    float*       dst = g_scratch + (size_t)b * HWD * CC;

    // Coalesced read: consecutive tx -> consecutive s
    #pragma unroll
    for (int j = 0; j < 32; j += 8) {
        int c = c0 + ty + j;
        int s = s0 + tx;
        if (s < HWD)
            tile[ty + j][tx] = src[c * HWD + s];
    }
    __syncthreads();

    // Coalesced write: consecutive tx -> consecutive c
    #pragma unroll
    for (int j = 0; j < 32; j += 8) {
        int s = s0 + ty + j;
        int c = c0 + tx;
        if (s < HWD)
            dst[s * CC + c] = tile[tx][ty + j];
    }
}

// ---------------------------------------------------------------------------
// Kernel 2: neighbor gather. One float4 per thread.
// idx layout: [b][p=h*38+w][n=di*3+dj][c4], c4 fastest -> fully coalesced
// 512B-contiguous reads and writes per warp.
// ---------------------------------------------------------------------------
__global__ void sp_gather_kernel(float4* __restrict__ out) {
    const int idx = blockIdx.x * blockDim.x + threadIdx.x;

    const int c4 = idx & (C4 - 1);
    const int r  = idx >> 7;          // (b,p,n) row id, 0..207935
    const int n  = r % 9;
    const int q  = r / 9;
    const int p  = q % HWD;
    const int b  = q / HWD;
    const int h  = p / WW;
    const int w  = p - h * WW;

    int sh = h + (n / 3) - 1;
    int sw = w + (n % 3) - 1;
    sh = min(max(sh, 0), HH - 1);     // replication padding
    sw = min(max(sw, 0), WW - 1);

    const float4* src = reinterpret_cast<const float4*>(g_scratch);
    float4 v = src[((size_t)b * HWD + sh * WW + sw) * C4 + c4];

    // Streaming store: output is write-once, don't let it evict scratch in L2.
    __stcs(out + idx, v);
}

// ---------------------------------------------------------------------------
extern "C" void kernel_launch(void* const* d_in, const int* in_sizes, int n_in,
                              void* d_out, int out_size) {
    const float* fm = (const float*)d_in[0];
    float4* out = (float4*)d_out;

    // Stage 1: transpose. 1444 = 45*32 + 4 -> 46 spatial tiles; 512/32 = 16.
    dim3 tgrid(46, 16, BB);
    dim3 tblock(32, 8);
    sp_transpose_kernel<<<tgrid, tblock>>>(fm);

    // Stage 2: gather. 16*1444*9*512 = 106,463,232 floats = 26,615,808 float4
    // 26615808 / 256 = 103968 blocks (exact)
    sp_gather_kernel<<<103968, 256>>>(out);
}

// round 4
// speedup vs baseline: 1.2965x; 1.2965x over previous
#include <cuda_runtime.h>

// SpatialPool fused: fm[16,512,38,38] f32 (NCHW) -> out[16,1444,9*512] f32
// out[b, h*38+w, (di*3+dj)*512 + c] = fm[b, c, clamp(h+di-1,0,37), clamp(w+dj-1,0,37)]
//
// Single kernel, scatter formulation: each block owns TS=32 source spatial
// positions x TC=128 channels. It loads them coalesced from NCHW (spatial dim
// is contiguous), transposes via padded smem, then writes each source channel
// vector to every output slot (p, n) whose clamped 3x3 neighbor is this source
// position. The destination map is an exact partition of the output, so every
// output element is written exactly once.

#define BB  16
#define CC  512
#define HH  38
#define WW  38
#define HWD 1444           // 38*38
#define OC  (9 * CC)       // 4608 output channels
#define TS  32             // source positions per block
#define TC  128            // channels per block
#define PAD 129            // TC+1, odd -> conflict-free smem both phases
#define NT  46             // ceil(1444/32) spatial tiles
#define NCH 4              // 512/128 channel chunks

__global__ __launch_bounds__(256, 8)
void sp_fused_kernel(const float* __restrict__ fm, float* __restrict__ out) {
    __shared__ float sm[TS * PAD];   // sm[i][c] : i = local source pos, c = channel

    const int s0   = blockIdx.x * TS;
    const int c0   = blockIdx.y * TC;
    const int b    = blockIdx.z;
    const int tid  = threadIdx.x;
    const int lane = tid & 31;
    const int wrp  = tid >> 5;

    const int ns = (HWD - s0 < TS) ? (HWD - s0) : TS;  // valid positions

    // ---- load + transpose: fm[b, c0+c, s0+lane] -> sm[lane][c]
    // warp reads 128B contiguous along spatial dim; smem banks (lane+c)%32.
    const float* src = fm + ((size_t)b * CC + c0) * HWD + s0;
    if (lane < ns) {
        #pragma unroll
        for (int c = wrp; c < TC; c += 8) {
            sm[lane * PAD + c] = __ldcs(src + (size_t)c * HWD + lane);
        }
    }
    __syncthreads();

    // ---- scatter: one (source pos i, neighbor n) pair per warp-iteration
    for (int t = wrp; t < ns * 9; t += 8) {
        const int i  = t / 9;
        const int n  = t - i * 9;
        const int di = n / 3;
        const int dj = n - di * 3;
        const int p  = s0 + i;          // source position (this is the CLAMPED pos)
        const int hq = p / WW;
        const int wq = p - hq * WW;

        // source channel vector (conflict-free LDS: banks (i+lane)%32)
        float v[4];
        #pragma unroll
        for (int j = 0; j < 4; j++)
            v[j] = sm[i * PAD + lane + 32 * j];

        // destinations: h with clamp(h + di - 1, 0, 37) == hq
        int hl[2]; int nh = 0;
        {
            int h0 = hq - di + 1;
            if (h0 >= 0 && h0 < HH) hl[nh++] = h0;
            if (hq == 0      && di == 0) hl[nh++] = 0;       // clamp(-1)  -> 0
            if (hq == HH - 1 && di == 2) hl[nh++] = HH - 1;  // clamp(38)  -> 37
        }
        int wl[2]; int nw = 0;
        {
            int w0 = wq - dj + 1;
            if (w0 >= 0 && w0 < WW) wl[nw++] = w0;
            if (wq == 0      && dj == 0) wl[nw++] = 0;
            if (wq == WW - 1 && dj == 2) wl[nw++] = WW - 1;
        }

        for (int a = 0; a < nh; a++) {
            for (int e = 0; e < nw; e++) {
                size_t base = ((size_t)b * HWD + hl[a] * WW + wl[e]) * OC
                            + n * CC + c0 + lane;
                // 4 x 128B coalesced streaming stores (write-once output)
                #pragma unroll
                for (int j = 0; j < 4; j++)
                    __stcs(out + base + 32 * j, v[j]);
            }
        }
    }
}

extern "C" void kernel_launch(void* const* d_in, const int* in_sizes, int n_in,
                              void* d_out, int out_size) {
    const float* fm = (const float*)d_in[0];
    float* out = (float*)d_out;

    dim3 grid(NT, NCH, BB);   // 46 x 4 x 16 = 2944 blocks
    sp_fused_kernel<<<grid, 256>>>(fm, out);
}

// round 7
// speedup vs baseline: 1.3305x; 1.0262x over previous
#include <cuda_runtime.h>

// SpatialPool fused: fm[16,512,38,38] f32 (NCHW) -> out[16,1444,9*512] f32
// out[b, h*38+w, (di*3+dj)*512 + c] = fm[b, c, clamp(h+di-1,0,37), clamp(w+dj-1,0,37)]
//
// Scatter formulation, fully 128-bit: block owns TS=32 source positions x
// TC=128 channels. Load coalesced from NCHW, pack 4 channels -> float4,
// store to XOR-swizzled smem (conflict-free STS.128 and LDS.128), then each
// warp scatters whole 512B channel vectors with single LDS.128 + STG.128
// per destination. Destination map is an exact partition of the output.

#define BB  16
#define CC  512
#define HH  38
#define WW  38
#define HWD 1444           // 38*38
#define OC4 1152           // 9*512/4 output float4 per row
#define CC4 128            // 512/4
#define TS  32             // source positions per block
#define TC  128            // channels per block (= 32 float4 groups)
#define NT  46             // ceil(1444/32)
#define NCH 4              // 512/128

__global__ __launch_bounds__(256, 8)
void sp_fused_kernel(const float* __restrict__ fm, float4* __restrict__ out) {
    // swizzled: logical (i, j) -> physical i*32 + (j ^ i), i,j in [0,32)
    __shared__ float4 sm4[TS * 32];   // 16 KB

    const int s0   = blockIdx.x * TS;
    const int c0   = blockIdx.y * TC;
    const int b    = blockIdx.z;
    const int lane = threadIdx.x & 31;
    const int wrp  = threadIdx.x >> 5;

    const int ns = (HWD - s0 < TS) ? (HWD - s0) : TS;

    // ---- load + transpose: lane = spatial i, warp covers 4 float4-groups
    const float* src = fm + ((size_t)b * CC + c0) * HWD + s0;
    if (lane < ns) {
        #pragma unroll
        for (int jj = 0; jj < 4; jj++) {
            const int j = wrp * 4 + jj;          // float4 channel group 0..31
            const float* p = src + (size_t)(4 * j) * HWD + lane;
            float4 v;
            v.x = __ldcs(p);                      // 4 coalesced 128B warp reads
            v.y = __ldcs(p + HWD);
            v.z = __ldcs(p + 2 * HWD);
            v.w = __ldcs(p + 3 * HWD);
            sm4[lane * 32 + (j ^ lane)] = v;      // conflict-free STS.128
        }
    }
    __syncthreads();

    const int c04 = c0 >> 2;

    // ---- scatter: one (source pos i, neighbor n) task per warp-iteration
    for (int t = wrp; t < ns * 9; t += 8) {
        const int i  = t / 9;
        const int n  = t - i * 9;
        const int di = n / 3;
        const int dj = n - di * 3;
        const int p  = s0 + i;                    // clamped source position
        const int hq = p / WW;
        const int wq = p - hq * WW;

        const float4 v = sm4[i * 32 + (lane ^ i)];  // conflict-free LDS.128

        // destinations: h with clamp(h + di - 1, 0, 37) == hq
        int hl[2]; int nh = 0;
        {
            const int h0 = hq - di + 1;
            if (h0 >= 0 && h0 < HH) hl[nh++] = h0;
            if (hq == 0      && di == 0) hl[nh++] = 0;       // clamp(-1) -> 0
            if (hq == HH - 1 && di == 2) hl[nh++] = HH - 1;  // clamp(38) -> 37
        }
        int wl[2]; int nw = 0;
        {
            const int w0 = wq - dj + 1;
            if (w0 >= 0 && w0 < WW) wl[nw++] = w0;
            if (wq == 0      && dj == 0) wl[nw++] = 0;
            if (wq == WW - 1 && dj == 2) wl[nw++] = WW - 1;
        }

        const size_t coff = (size_t)(n * CC4 + c04 + lane);
        for (int a = 0; a < nh; a++) {
            const size_t rbase = ((size_t)b * HWD + hl[a] * WW) * OC4 + coff;
            for (int e = 0; e < nw; e++) {
                // single 512B coalesced streaming store per warp
                __stcs(out + rbase + (size_t)wl[e] * OC4, v);
            }
        }
    }
}

extern "C" void kernel_launch(void* const* d_in, const int* in_sizes, int n_in,
                              void* d_out, int out_size) {
    const float* fm = (const float*)d_in[0];
    float4* out = (float4*)d_out;

    dim3 grid(NT, NCH, BB);   // 46 x 4 x 16 = 2944 blocks
    sp_fused_kernel<<<grid, 256>>>(fm, out);
}

// round 9
// speedup vs baseline: 1.4408x; 1.0829x over previous
#include <cuda_runtime.h>

// SpatialPool fused: fm[16,512,38,38] f32 (NCHW) -> out[16,1444,9*512] f32
// out[b, h*38+w, (di*3+dj)*512 + c] = fm[b, c, clamp(h+di-1,0,37), clamp(w+dj-1,0,37)]
//
// Scatter formulation: block owns TS=32 source positions x TC=128 channels.
// Coalesced NCHW load -> float4 pack -> XOR-swizzled smem transpose.
// Scatter: one warp per source position; decode + LDS once, unrolled
// 9-neighbor loop with predicated (primary/duplicate) destination offsets.
// The destination map is an exact partition of the output.

#define BB  16
#define CC  512
#define HH  38
#define WW  38
#define HWD 1444           // 38*38
#define OC4 1152           // 9*512/4 float4 per output row
#define CC4 128            // 512/4
#define ROW (WW * OC4)     // float4 per h-row
#define TS  32
#define TC  128
#define NT  46             // ceil(1444/32)
#define NCH 4              // 512/128

__global__ __launch_bounds__(256, 8)
void sp_fused_kernel(const float* __restrict__ fm, float4* __restrict__ out) {
    // swizzled: logical (i, j) -> physical i*32 + (j ^ i)
    __shared__ float4 sm4[TS * 32];   // 16 KB

    const int s0   = blockIdx.x * TS;
    const int c0   = blockIdx.y * TC;
    const int b    = blockIdx.z;
    const int lane = threadIdx.x & 31;
    const int wrp  = threadIdx.x >> 5;

    const int ns = (HWD - s0 < TS) ? (HWD - s0) : TS;

    // ---- load + transpose: lane = spatial i, warp covers 4 float4-groups
    const float* src = fm + ((size_t)b * CC + c0) * HWD + s0;
    if (lane < ns) {
        #pragma unroll
        for (int jj = 0; jj < 4; jj++) {
            const int j = wrp * 4 + jj;
            const float* p = src + (size_t)(4 * j) * HWD + lane;
            float4 v;
            v.x = __ldcs(p);
            v.y = __ldcs(p + HWD);
            v.z = __ldcs(p + 2 * HWD);
            v.w = __ldcs(p + 3 * HWD);
            sm4[lane * 32 + (j ^ lane)] = v;      // conflict-free STS.128
        }
    }
    __syncthreads();

    const int pbase0 = b * (HWD * OC4) + (c0 >> 2) + lane;  // < 2^25, fits int

    // ---- scatter: one source position per warp-iteration (4 per warp)
    #pragma unroll
    for (int i0 = 0; i0 < 4; i0++) {
        const int i = wrp + 8 * i0;
        if (i >= ns) break;
        const int p  = s0 + i;
        const int hq = p / WW;
        const int wq = p - hq * WW;

        const float4 v = sm4[i * 32 + (lane ^ i)];   // single LDS.128, reused x9

        // clamp-inverse destination classes: primary (hv) + duplicate (hd)
        // di=0 (delta=-1): h=hq+1 if hq<37; dup h=0 if hq==0   (hq=37: none)
        // di=1 (delta= 0): h=hq always
        // di=2 (delta=+1): h=hq-1 if hq>0;  dup h=37 if hq==37 (hq=0: none)
        int  hoffP[3], hoffD[3];
        bool hv[3], hd[3];
        hv[0] = (hq < HH - 1);  hoffP[0] = (hq + 1) * ROW;
        hd[0] = (hq == 0);      hoffD[0] = 0;
        hv[1] = true;           hoffP[1] = hq * ROW;
        hd[1] = false;          hoffD[1] = 0;
        hv[2] = (hq > 0);       hoffP[2] = (hq - 1) * ROW;
        hd[2] = (hq == HH - 1); hoffD[2] = (HH - 1) * ROW;

        int  woffP[3], woffD[3];
        bool wv[3], wd[3];
        wv[0] = (wq < WW - 1);  woffP[0] = (wq + 1) * OC4;
        wd[0] = (wq == 0);      woffD[0] = 0;
        wv[1] = true;           woffP[1] = wq * OC4;
        wd[1] = false;          woffD[1] = 0;
        wv[2] = (wq > 0);       woffP[2] = (wq - 1) * OC4;
        wd[2] = (wq == WW - 1); woffD[2] = (WW - 1) * OC4;

        #pragma unroll
        for (int n = 0; n < 9; n++) {
            const int di = n / 3;
            const int dj = n - di * 3;
            const int base_n = pbase0 + n * CC4;

            if (hv[di] && wv[dj])
                __stcs(out + (base_n + hoffP[di] + woffP[dj]), v);
            if (hd[di] && wv[dj])
                __stcs(out + (base_n + hoffD[di] + woffP[dj]), v);
            if (hv[di] && wd[dj])
                __stcs(out + (base_n + hoffP[di] + woffD[dj]), v);
            if (hd[di] && wd[dj])
                __stcs(out + (base_n + hoffD[di] + woffD[dj]), v);
        }
    }
}

extern "C" void kernel_launch(void* const* d_in, const int* in_sizes, int n_in,
                              void* d_out, int out_size) {
    const float* fm = (const float*)d_in[0];
    float4* out = (float4*)d_out;

    dim3 grid(NT, NCH, BB);   // 46 x 4 x 16 = 2944 blocks
    sp_fused_kernel<<<grid, 256>>>(fm, out);
}

// round 10
// speedup vs baseline: 1.4780x; 1.0259x over previous
#include <cuda_runtime.h>

// SpatialPool fused: fm[16,512,38,38] f32 (NCHW) -> out[16,1444,9*512] f32
// out[b, h*38+w, (di*3+dj)*512 + c] = fm[b, c, clamp(h+di-1,0,37), clamp(w+dj-1,0,37)]
//
// Scatter formulation: block owns TS=16 source positions x TC=128 channels
// (finer spatial tiling -> 5824 blocks -> ~4.9 waves, tiny tail vs 2.49).
// Coalesced NCHW load -> float4 pack -> XOR-swizzled smem transpose.
// Scatter: one warp per source position; decode + LDS once, unrolled
// 9-neighbor loop with predicated (primary/duplicate) destination offsets.
// The destination map is an exact partition of the output.

#define BB  16
#define CC  512
#define HH  38
#define WW  38
#define HWD 1444           // 38*38
#define OC4 1152           // 9*512/4 float4 per output row
#define CC4 128            // 512/4
#define ROW (WW * OC4)     // float4 per h-row
#define TS  16
#define TC  128
#define NT  91             // ceil(1444/16): 90 full tiles + one of 4
#define NCH 4              // 512/128

__global__ __launch_bounds__(256, 8)
void sp_fused_kernel(const float* __restrict__ fm, float4* __restrict__ out) {
    // swizzled: logical (i, j) -> physical i*32 + (j ^ i), i<16, j<32
    __shared__ float4 sm4[TS * 32];   // 8 KB

    const int s0   = blockIdx.x * TS;
    const int c0   = blockIdx.y * TC;
    const int b    = blockIdx.z;
    const int lane = threadIdx.x & 31;
    const int wrp  = threadIdx.x >> 5;

    const int ns = (HWD - s0 < TS) ? (HWD - s0) : TS;

    // ---- load + transpose: lanes 0..15 = spatial i, warp covers 4 f4-groups
    const float* src = fm + ((size_t)b * CC + c0) * HWD + s0;
    if (lane < ns) {
        #pragma unroll
        for (int jj = 0; jj < 4; jj++) {
            const int j = wrp * 4 + jj;            // float4 channel group 0..31
            const float* p = src + (size_t)(4 * j) * HWD + lane;
            float4 v;
            v.x = __ldcs(p);
            v.y = __ldcs(p + HWD);
            v.z = __ldcs(p + 2 * HWD);
            v.w = __ldcs(p + 3 * HWD);
            sm4[lane * 32 + (j ^ lane)] = v;       // conflict-free STS.128
        }
    }
    __syncthreads();

    const int pbase0 = b * (HWD * OC4) + (c0 >> 2) + lane;  // < 2^25, fits int

    // ---- scatter: one source position per warp-iteration (2 per warp)
    #pragma unroll
    for (int i0 = 0; i0 < 2; i0++) {
        const int i = wrp + 8 * i0;
        if (i >= ns) break;
        const int p  = s0 + i;
        const int hq = p / WW;
        const int wq = p - hq * WW;

        const float4 v = sm4[i * 32 + (lane ^ i)];   // one LDS.128, reused x9

        // clamp-inverse destination classes: primary (hv) + duplicate (hd)
        // di=0 (delta=-1): h=hq+1 if hq<37; dup h=0 if hq==0   (hq=37: none)
        // di=1 (delta= 0): h=hq always
        // di=2 (delta=+1): h=hq-1 if hq>0;  dup h=37 if hq==37 (hq=0: none)
        int  hoffP[3], hoffD[3];
        bool hv[3], hd[3];
        hv[0] = (hq < HH - 1);  hoffP[0] = (hq + 1) * ROW;
        hd[0] = (hq == 0);      hoffD[0] = 0;
        hv[1] = true;           hoffP[1] = hq * ROW;
        hd[1] = false;          hoffD[1] = 0;
        hv[2] = (hq > 0);       hoffP[2] = (hq - 1) * ROW;
        hd[2] = (hq == HH - 1); hoffD[2] = (HH - 1) * ROW;

        int  woffP[3], woffD[3];
        bool wv[3], wd[3];
        wv[0] = (wq < WW - 1);  woffP[0] = (wq + 1) * OC4;
        wd[0] = (wq == 0);      woffD[0] = 0;
        wv[1] = true;           woffP[1] = wq * OC4;
        wd[1] = false;          woffD[1] = 0;
        wv[2] = (wq > 0);       woffP[2] = (wq - 1) * OC4;
        wd[2] = (wq == WW - 1); woffD[2] = (WW - 1) * OC4;

        #pragma unroll
        for (int n = 0; n < 9; n++) {
            const int di = n / 3;
            const int dj = n - di * 3;
            const int base_n = pbase0 + n * CC4;

            if (hv[di] && wv[dj])
                __stcs(out + (base_n + hoffP[di] + woffP[dj]), v);
            if (hd[di] && wv[dj])
                __stcs(out + (base_n + hoffD[di] + woffP[dj]), v);
            if (hv[di] && wd[dj])
                __stcs(out + (base_n + hoffP[di] + woffD[dj]), v);
            if (hd[di] && wd[dj])
                __stcs(out + (base_n + hoffD[di] + woffD[dj]), v);
        }
    }
}

extern "C" void kernel_launch(void* const* d_in, const int* in_sizes, int n_in,
                              void* d_out, int out_size) {
    const float* fm = (const float*)d_in[0];
    float4* out = (float4*)d_out;

    dim3 grid(NT, NCH, BB);   // 91 x 4 x 16 = 5824 blocks, ~4.9 waves
    sp_fused_kernel<<<grid, 256>>>(fm, out);
}

// round 12
// speedup vs baseline: 1.5192x; 1.0279x over previous
#include <cuda_runtime.h>

// SpatialPool fused: fm[16,512,38,38] f32 (NCHW) -> out[16,1444,9*512] f32
// out[b, h*38+w, (di*3+dj)*512 + c] = fm[b, c, clamp(h+di-1,0,37), clamp(w+dj-1,0,37)]
//
// Scatter formulation with 2KB-contiguous warp stores: each block owns TS=4
// source positions x ALL 512 channels (1444 = 4*361, exact tiling).
// Load coalesced from NCHW into XOR-swizzled float4 smem; scatter with one
// warp per (position, neighbor-parity): a warp writes the full 2KB channel
// vector of a neighbor slot as 4 consecutive STG.128 (contiguous 2048B),
// improving the L2->HBM dirty-eviction burst locality.
// Destination map is an exact partition of the output.

#define BB  16
#define CC  512
#define HH  38
#define WW  38
#define HWD 1444           // 38*38
#define OC4 1152           // 9*512/4 float4 per output row
#define CC4 128            // 512/4
#define ROW (WW * OC4)
#define TS  4
#define NT  361            // 1444 / 4 exact

__global__ __launch_bounds__(256)
void sp_fused_kernel(const float* __restrict__ fm, float4* __restrict__ out) {
    // swizzled: logical (i<4, j<128) -> physical i*128 + (j ^ (2*i))
    // STS phase lanes (i = lane&3, jsub = lane>>2): per 8-lane phase banks
    // (jsub ^ 2i) & 7 are distinct. LDS phase (fixed i, j = lane+32m):
    // banks (lane ^ 2i) & 7 distinct per phase. Conflict-free both ways.
    __shared__ float4 sm4[TS * 128];   // 8 KB

    const int s0   = blockIdx.x * TS;
    const int b    = blockIdx.y;
    const int lane = threadIdx.x & 31;
    const int wrp  = threadIdx.x >> 5;

    // ---- load + transpose: lane -> (position i, channel-f4 subgroup jsub)
    {
        const int li   = lane & 3;          // position within tile
        const int jsub = lane >> 2;         // f4-group 0..7 within warp slice
        const float* src = fm + (size_t)b * CC * HWD + s0 + li;
        #pragma unroll
        for (int it = 0; it < 2; it++) {
            const int j = wrp * 16 + it * 8 + jsub;   // f4 channel group 0..127
            const float* p = src + (size_t)(4 * j) * HWD;
            float4 v;
            v.x = __ldcs(p);
            v.y = __ldcs(p + HWD);
            v.z = __ldcs(p + 2 * HWD);
            v.w = __ldcs(p + 3 * HWD);
            sm4[li * 128 + (j ^ (2 * li))] = v;        // conflict-free STS.128
        }
    }
    __syncthreads();

    // ---- scatter: warp -> (position i, neighbor parity)
    const int i    = wrp >> 1;          // 0..3
    const int wpar = wrp & 1;           // even/odd neighbors
    const int p    = s0 + i;
    const int hq   = p / WW;
    const int wq   = p - hq * WW;

    // whole 512-channel vector for this position (4 conflict-free LDS.128)
    float4 v[4];
    #pragma unroll
    for (int m = 0; m < 4; m++)
        v[m] = sm4[i * 128 + ((lane + 32 * m) ^ (2 * i))];

    // clamp-inverse destination classes: primary (hv) + duplicate (hd)
    // di=0 (delta=-1): h=hq+1 if hq<37; dup h=0 if hq==0   (hq=37: none)
    // di=1 (delta= 0): h=hq always
    // di=2 (delta=+1): h=hq-1 if hq>0;  dup h=37 if hq==37 (hq=0: none)
    int  hoffP[3], hoffD[3];
    bool hv[3], hd[3];
    hv[0] = (hq < HH - 1);  hoffP[0] = (hq + 1) * ROW;
    hd[0] = (hq == 0);      hoffD[0] = 0;
    hv[1] = true;           hoffP[1] = hq * ROW;
    hd[1] = false;          hoffD[1] = 0;
    hv[2] = (hq > 0);       hoffP[2] = (hq - 1) * ROW;
    hd[2] = (hq == HH - 1); hoffD[2] = (HH - 1) * ROW;

    int  woffP[3], woffD[3];
    bool wv[3], wd[3];
    wv[0] = (wq < WW - 1);  woffP[0] = (wq + 1) * OC4;
    wd[0] = (wq == 0);      woffD[0] = 0;
    wv[1] = true;           woffP[1] = wq * OC4;
    wd[1] = false;          woffD[1] = 0;
    wv[2] = (wq > 0);       woffP[2] = (wq - 1) * OC4;
    wd[2] = (wq == WW - 1); woffD[2] = (WW - 1) * OC4;

    const int pbase0 = b * (HWD * OC4) + lane;   // max < 2^25, fits int

    #pragma unroll
    for (int n = 0; n < 9; n++) {
        if ((n & 1) != wpar) continue;           // parity split across 2 warps
        const int di = n / 3;
        const int dj = n - di * 3;
        const int base_n = pbase0 + n * CC4;

        if (hv[di] && wv[dj]) {
            const int o = base_n + hoffP[di] + woffP[dj];
            #pragma unroll
            for (int m = 0; m < 4; m++) __stcs(out + o + 32 * m, v[m]);
        }
        if (hd[di] && wv[dj]) {
            const int o = base_n + hoffD[di] + woffP[dj];
            #pragma unroll
            for (int m = 0; m < 4; m++) __stcs(out + o + 32 * m, v[m]);
        }
        if (hv[di] && wd[dj]) {
            const int o = base_n + hoffP[di] + woffD[dj];
            #pragma unroll
            for (int m = 0; m < 4; m++) __stcs(out + o + 32 * m, v[m]);
        }
        if (hd[di] && wd[dj]) {
            const int o = base_n + hoffD[di] + woffD[dj];
            #pragma unroll
            for (int m = 0; m < 4; m++) __stcs(out + o + 32 * m, v[m]);
        }
    }
}

extern "C" void kernel_launch(void* const* d_in, const int* in_sizes, int n_in,
                              void* d_out, int out_size) {
    const float* fm = (const float*)d_in[0];
    float4* out = (float4*)d_out;

    dim3 grid(NT, BB);   // 361 x 16 = 5776 blocks
    sp_fused_kernel<<<grid, 256>>>(fm, out);
}